// round 3
// baseline (speedup 1.0000x reference)
#include <cuda_runtime.h>
#include <math.h>

typedef unsigned long long ull;

#define B_ 16
#define D_ 512
#define K_ 64
#define N_ 4096
#define NSPLIT 8

// ---------------- scratch (device globals: no runtime allocation) ----------
__device__ float g_S[(size_t)B_ * K_ * N_];                 // softmax scores [b][k][n]
__device__ float g_ssum[B_ * K_];                           // sum_n S
__device__ float g_part[(size_t)NSPLIT * B_ * D_ * K_];     // agg partials [ns][b][d][k]
__device__ float g_bnorm[B_];                               // per-b global sum-of-squares

// ---------------- packed f32x2 helpers -------------------------------------
__device__ __forceinline__ ull pk(float x, float y) {
    ull r; asm("mov.b64 %0, {%1, %2};" : "=l"(r) : "f"(x), "f"(y)); return r;
}
__device__ __forceinline__ void upk(ull v, float& x, float& y) {
    asm("mov.b64 {%0, %1}, %2;" : "=f"(x), "=f"(y) : "l"(v));
}
__device__ __forceinline__ ull ffma2(ull a, ull b, ull c) {
    ull d; asm("fma.rn.f32x2 %0, %1, %2, %3;" : "=l"(d) : "l"(a), "l"(b), "l"(c));
    return d;
}

// ---------------- k0: zero accumulators ------------------------------------
__global__ void k0_zero() {
    int t = blockIdx.x * 256 + threadIdx.x;
    if (t < B_ * K_) g_ssum[t] = 0.f;
    if (t < B_)      g_bnorm[t] = 0.f;
}

// ---------------- k1: logits GEMM + softmax + ssum --------------------------
// grid: (N_/256, B_), block 256. Tile: 64 k-rows x 256 n-cols, reduce D in 32s.
// warp w owns k rows [8w, 8w+8); lane owns n pairs jp*64 + lane*2 (+1), jp=0..3.
__global__ __launch_bounds__(256, 2)
void k1_scores(const float* __restrict__ desc, const float* __restrict__ W,
               const float* __restrict__ bias)
{
    const int b    = blockIdx.y;
    const int n0   = blockIdx.x * 256;
    const int t    = threadIdx.x;
    const int lane = t & 31;
    const int w    = t >> 5;

    // sWred: W tile [64][33] during GEMM; red buffer (float2[8][128]) afterwards
    __shared__ __align__(16) float sWred[64 * 33];   // 2112 floats >= 2048 for red
    __shared__ __align__(16) float sX[32 * 256];     // desc chunk [dc][n]

    const float* __restrict__ dB = desc + (size_t)b * D_ * N_;

    ull acc2[8][4];
    const ull z2 = pk(0.f, 0.f);
    #pragma unroll
    for (int i = 0; i < 8; i++)
        #pragma unroll
        for (int jp = 0; jp < 4; jp++) acc2[i][jp] = z2;

    for (int d0 = 0; d0 < D_; d0 += 32) {
        // fill W chunk: [k][dc], stride 33 (conflict-free store)
        #pragma unroll
        for (int r = 0; r < 8; r++) {
            int idx = r * 256 + t;
            int k = idx >> 5, dc = idx & 31;
            sWred[k * 33 + dc] = W[k * D_ + d0 + dc];
        }
        // fill X chunk: [dc][n], float4 coalesced
        #pragma unroll
        for (int r = 0; r < 8; r++) {
            int idx = r * 256 + t;
            int dc = idx >> 6, n4 = idx & 63;
            float4 v = *reinterpret_cast<const float4*>(
                dB + (size_t)(d0 + dc) * N_ + n0 + n4 * 4);
            *reinterpret_cast<float4*>(sX + dc * 256 + n4 * 4) = v;
        }
        __syncthreads();
        #pragma unroll 4
        for (int dc = 0; dc < 32; dc++) {
            ull xv[4];
            #pragma unroll
            for (int jp = 0; jp < 4; jp++)
                xv[jp] = *reinterpret_cast<const ull*>(sX + dc * 256 + jp * 64 + lane * 2);
            #pragma unroll
            for (int i = 0; i < 8; i++) {
                float wv = sWred[(w * 8 + i) * 33 + dc];   // warp-broadcast
                ull wv2 = pk(wv, wv);
                #pragma unroll
                for (int jp = 0; jp < 4; jp++)
                    acc2[i][jp] = ffma2(wv2, xv[jp], acc2[i][jp]);
            }
        }
        __syncthreads();
    }

    // unpack + bias
    float a[8][8];
    #pragma unroll
    for (int i = 0; i < 8; i++) {
        float bb = bias[w * 8 + i];
        #pragma unroll
        for (int jp = 0; jp < 4; jp++) {
            float x, y; upk(acc2[i][jp], x, y);
            a[i][2 * jp]     = x + bb;
            a[i][2 * jp + 1] = y + bb;
        }
    }

    float2* red2 = reinterpret_cast<float2*>(sWred);   // [8 warps][128 pair-cols]
    float fx[4], fy[4];

    // column max over all 64 k (per-warp partial, then cross-warp)
    #pragma unroll
    for (int jp = 0; jp < 4; jp++) {
        float mx = a[0][2 * jp], my = a[0][2 * jp + 1];
        #pragma unroll
        for (int i = 1; i < 8; i++) {
            mx = fmaxf(mx, a[i][2 * jp]);
            my = fmaxf(my, a[i][2 * jp + 1]);
        }
        red2[w * 128 + jp * 32 + lane] = make_float2(mx, my);
    }
    __syncthreads();
    #pragma unroll
    for (int jp = 0; jp < 4; jp++) {
        float2 m = red2[jp * 32 + lane];
        #pragma unroll
        for (int ww = 1; ww < 8; ww++) {
            float2 o = red2[ww * 128 + jp * 32 + lane];
            m.x = fmaxf(m.x, o.x); m.y = fmaxf(m.y, o.y);
        }
        fx[jp] = m.x; fy[jp] = m.y;
    }
    __syncthreads();

    // exp + column sum
    #pragma unroll
    for (int jp = 0; jp < 4; jp++) {
        float sx = 0.f, sy = 0.f;
        #pragma unroll
        for (int i = 0; i < 8; i++) {
            float ex = __expf(a[i][2 * jp]     - fx[jp]);
            float ey = __expf(a[i][2 * jp + 1] - fy[jp]);
            a[i][2 * jp] = ex; a[i][2 * jp + 1] = ey;
            sx += ex; sy += ey;
        }
        red2[w * 128 + jp * 32 + lane] = make_float2(sx, sy);
    }
    __syncthreads();
    #pragma unroll
    for (int jp = 0; jp < 4; jp++) {
        float2 s = red2[jp * 32 + lane];
        #pragma unroll
        for (int ww = 1; ww < 8; ww++) {
            float2 o = red2[ww * 128 + jp * 32 + lane];
            s.x += o.x; s.y += o.y;
        }
        fx[jp] = 1.f / s.x; fy[jp] = 1.f / s.y;   // reuse as inverse sums
    }

    // normalize, store S (coalesced float2), accumulate ssum
    float* Sb = g_S + (size_t)b * K_ * N_;
    #pragma unroll
    for (int i = 0; i < 8; i++) {
        float srow = 0.f;
        float* row = Sb + (size_t)(w * 8 + i) * N_ + n0;
        #pragma unroll
        for (int jp = 0; jp < 4; jp++) {
            float px = a[i][2 * jp] * fx[jp];
            float py = a[i][2 * jp + 1] * fy[jp];
            srow += px + py;
            *reinterpret_cast<float2*>(row + jp * 64 + lane * 2) = make_float2(px, py);
        }
        #pragma unroll
        for (int o = 16; o > 0; o >>= 1)
            srow += __shfl_xor_sync(0xffffffffu, srow, o);
        if (lane == 0) atomicAdd(&g_ssum[b * K_ + w * 8 + i], srow);
    }
}

// ---------------- k2: agg GEMM (desc @ S^T), n-split into partials ----------
// grid: (D_/256, NSPLIT, B_), block 256. Tile 64 k x 256 d, reduce n in 32s.
__global__ __launch_bounds__(256, 2)
void k2_agg(const float* __restrict__ desc)
{
    const int b    = blockIdx.z;
    const int ns   = blockIdx.y;
    const int d0   = blockIdx.x * 256;
    const int t    = threadIdx.x;
    const int lane = t & 31;
    const int w    = t >> 5;

    __shared__ __align__(16) float sS[32 * 65];   // [nc][k], pad 65
    __shared__ __align__(16) float sDO[8320];     // sD[32][258] / sOut[128][65]

    const float* __restrict__ dB = desc + (size_t)b * D_ * N_;
    const float* __restrict__ Sb = g_S + (size_t)b * K_ * N_;

    ull acc2[8][4];
    const ull z2 = pk(0.f, 0.f);
    #pragma unroll
    for (int i = 0; i < 8; i++)
        #pragma unroll
        for (int jp = 0; jp < 4; jp++) acc2[i][jp] = z2;

    const int nbase = ns * (N_ / NSPLIT);   // 512 n per block
    for (int nb = 0; nb < N_ / NSPLIT; nb += 32) {
        const int n0c = nbase + nb;
        // fill S chunk [nc][k] (coalesced read over k, conflict-free store)
        #pragma unroll
        for (int r = 0; r < 8; r++) {
            int idx = r * 256 + t;
            int k = idx >> 5, nc = idx & 31;
            sS[nc * 65 + k] = Sb[(size_t)k * N_ + n0c + nc];
        }
        // fill D chunk [nc][d], stride 258; float4 reads along n
        #pragma unroll
        for (int r = 0; r < 8; r++) {
            int idx = r * 256 + t;
            int dl = idx >> 3, q = idx & 7;
            float4 v = *reinterpret_cast<const float4*>(
                dB + (size_t)(d0 + dl) * N_ + n0c + q * 4);
            sDO[(q * 4 + 0) * 258 + dl] = v.x;
            sDO[(q * 4 + 1) * 258 + dl] = v.y;
            sDO[(q * 4 + 2) * 258 + dl] = v.z;
            sDO[(q * 4 + 3) * 258 + dl] = v.w;
        }
        __syncthreads();
        #pragma unroll 4
        for (int nc = 0; nc < 32; nc++) {
            ull dv[4];
            #pragma unroll
            for (int jp = 0; jp < 4; jp++)
                dv[jp] = *reinterpret_cast<const ull*>(sDO + nc * 258 + jp * 64 + lane * 2);
            #pragma unroll
            for (int i = 0; i < 8; i++) {
                float kv = sS[nc * 65 + w * 8 + i];   // warp-broadcast
                ull kv2 = pk(kv, kv);
                #pragma unroll
                for (int jp = 0; jp < 4; jp++)
                    acc2[i][jp] = ffma2(kv2, dv[jp], acc2[i][jp]);
            }
        }
        __syncthreads();
    }

    // stage through shared for coalesced [d][k] stores, two 128-d halves
    float* outp = g_part + ((size_t)ns * B_ + b) * (D_ * K_);
    #pragma unroll
    for (int half = 0; half < 2; half++) {
        #pragma unroll
        for (int i = 0; i < 8; i++) {
            #pragma unroll
            for (int jl = 0; jl < 2; jl++) {
                int jp = half * 2 + jl;
                float x, y; upk(acc2[i][jp], x, y);
                int dl = jl * 64 + lane * 2;
                sDO[(dl    ) * 65 + w * 8 + i] = x;
                sDO[(dl + 1) * 65 + w * 8 + i] = y;
            }
        }
        __syncthreads();
        #pragma unroll
        for (int r = 0; r < 32; r++) {
            int idx = r * 256 + t;
            int dl = idx >> 6, k = idx & 63;
            outp[(size_t)(d0 + half * 128 + dl) * K_ + k] = sDO[dl * 65 + k];
        }
        __syncthreads();
    }
}

// ---------------- k3: combine partials, subtract centers*ssum, intra-norm ---
// grid: (B_, 4), block 256 = (16 kk x 16 rr); each thread covers 32 d values.
__global__ void k3_vlad(const float* __restrict__ centers, float* __restrict__ out)
{
    const int b  = blockIdx.x;
    const int kg = blockIdx.y;
    const int t  = threadIdx.x;
    const int kk = t & 15;
    const int rr = t >> 4;
    const int k  = kg * 16 + kk;
    const float ss = g_ssum[b * K_ + k];

    float* ob = out + (size_t)b * (D_ * K_);
    float sq = 0.f;
    #pragma unroll 4
    for (int q = 0; q < 32; q++) {
        int d = rr * 32 + q;
        int off = d * K_ + k;
        float s = 0.f;
        #pragma unroll
        for (int ns = 0; ns < NSPLIT; ns++)
            s += g_part[((size_t)ns * B_ + b) * (D_ * K_) + off];
        float v = s - centers[off] * ss;
        ob[off] = v;
        sq += v * v;
    }

    __shared__ float sred[256];
    __shared__ float sinv[16];
    sred[t] = sq;
    __syncthreads();
    for (int s2 = 128; s2 >= 16; s2 >>= 1) {
        if (t < s2) sred[t] += sred[t + s2];
        __syncthreads();
    }
    if (t < 16) {
        float tot = sred[t];
        float inv = 1.f / fmaxf(sqrtf(tot), 1e-12f);
        sinv[t] = inv;
        atomicAdd(&g_bnorm[b], tot * inv * inv);
    }
    __syncthreads();
    float inv = sinv[kk];
    #pragma unroll 4
    for (int q = 0; q < 32; q++) {
        int off = (rr * 32 + q) * K_ + k;
        ob[off] *= inv;
    }
}

// ---------------- k4: global L2 normalize ----------------------------------
__global__ void k4_gnorm(float* __restrict__ out)
{
    int idx = blockIdx.x * 256 + threadIdx.x;
    float inv = 1.f / fmaxf(sqrtf(g_bnorm[idx >> 15]), 1e-12f);
    out[idx] *= inv;
}

// ---------------- launch -----------------------------------------------------
extern "C" void kernel_launch(void* const* d_in, const int* in_sizes, int n_in,
                              void* d_out, int out_size)
{
    const float* desc    = (const float*)d_in[0];   // [16,512,4096]
    const float* W       = (const float*)d_in[1];   // [64,512]
    const float* bias    = (const float*)d_in[2];   // [64]
    const float* centers = (const float*)d_in[3];   // [512,64]
    float* out = (float*)d_out;                      // [16, 512*64]

    k0_zero<<<4, 256>>>();
    k1_scores<<<dim3(N_ / 256, B_), 256>>>(desc, W, bias);
    k2_agg<<<dim3(D_ / 256, NSPLIT, B_), 256>>>(desc);
    k3_vlad<<<dim3(B_, 4), 256>>>(centers, out);
    k4_gnorm<<<(B_ * D_ * K_) / 256, 256>>>(out);
}

// round 5
// speedup vs baseline: 1.7234x; 1.7234x over previous
#include <cuda_runtime.h>
#include <cuda_bf16.h>
#include <math.h>
#include <stdint.h>

typedef unsigned long long ull;

#define B_ 16
#define D_ 512
#define K_ 64
#define N_ 4096
#define NSPLIT 4

// ---------------- scratch (device globals: no runtime allocation) ----------
__device__ __nv_bfloat16 g_Sbf[(size_t)B_ * K_ * N_];       // softmax scores bf16 [b][k][n]
__device__ float g_ssum[B_ * K_];                           // sum_n S (fp32)
__device__ float g_part[(size_t)NSPLIT * B_ * D_ * K_];     // agg partials [ns][b][d][k]
__device__ float g_bnorm[B_];                               // per-b global sum-of-squares

// ---------------- packed f32x2 helpers (k1) --------------------------------
__device__ __forceinline__ ull pk(float x, float y) {
    ull r; asm("mov.b64 %0, {%1, %2};" : "=l"(r) : "f"(x), "f"(y)); return r;
}
__device__ __forceinline__ void upk(ull v, float& x, float& y) {
    asm("mov.b64 {%0, %1}, %2;" : "=f"(x), "=f"(y) : "l"(v));
}
__device__ __forceinline__ ull ffma2(ull a, ull b, ull c) {
    ull d; asm("fma.rn.f32x2 %0, %1, %2, %3;" : "=l"(d) : "l"(a), "l"(b), "l"(c));
    return d;
}

__device__ __forceinline__ unsigned smem_u32(const void* p) {
    unsigned a;
    asm("{ .reg .u64 t; cvta.to.shared.u64 t, %1; cvt.u32.u64 %0, t; }" : "=r"(a) : "l"(p));
    return a;
}

// ---------------- k0: zero accumulators ------------------------------------
__global__ void k0_zero() {
    int t = blockIdx.x * 256 + threadIdx.x;
    if (t < B_ * K_) g_ssum[t] = 0.f;
    if (t < B_)      g_bnorm[t] = 0.f;
}

// ---------------- k1: logits GEMM + softmax + ssum (f32x2), S -> bf16 -------
__global__ __launch_bounds__(256, 2)
void k1_scores(const float* __restrict__ desc, const float* __restrict__ W,
               const float* __restrict__ bias)
{
    const int b    = blockIdx.y;
    const int n0   = blockIdx.x * 256;
    const int t    = threadIdx.x;
    const int lane = t & 31;
    const int w    = t >> 5;

    __shared__ __align__(16) float sWred[64 * 33];
    __shared__ __align__(16) float sX[32 * 256];

    const float* __restrict__ dB = desc + (size_t)b * D_ * N_;

    ull acc2[8][4];
    const ull z2 = pk(0.f, 0.f);
    #pragma unroll
    for (int i = 0; i < 8; i++)
        #pragma unroll
        for (int jp = 0; jp < 4; jp++) acc2[i][jp] = z2;

    for (int d0 = 0; d0 < D_; d0 += 32) {
        #pragma unroll
        for (int r = 0; r < 8; r++) {
            int idx = r * 256 + t;
            int k = idx >> 5, dc = idx & 31;
            sWred[k * 33 + dc] = W[k * D_ + d0 + dc];
        }
        #pragma unroll
        for (int r = 0; r < 8; r++) {
            int idx = r * 256 + t;
            int dc = idx >> 6, n4 = idx & 63;
            float4 v = *reinterpret_cast<const float4*>(
                dB + (size_t)(d0 + dc) * N_ + n0 + n4 * 4);
            *reinterpret_cast<float4*>(sX + dc * 256 + n4 * 4) = v;
        }
        __syncthreads();
        #pragma unroll 4
        for (int dc = 0; dc < 32; dc++) {
            ull xv[4];
            #pragma unroll
            for (int jp = 0; jp < 4; jp++)
                xv[jp] = *reinterpret_cast<const ull*>(sX + dc * 256 + jp * 64 + lane * 2);
            #pragma unroll
            for (int i = 0; i < 8; i++) {
                float wv = sWred[(w * 8 + i) * 33 + dc];
                ull wv2 = pk(wv, wv);
                #pragma unroll
                for (int jp = 0; jp < 4; jp++)
                    acc2[i][jp] = ffma2(wv2, xv[jp], acc2[i][jp]);
            }
        }
        __syncthreads();
    }

    float a[8][8];
    #pragma unroll
    for (int i = 0; i < 8; i++) {
        float bb = bias[w * 8 + i];
        #pragma unroll
        for (int jp = 0; jp < 4; jp++) {
            float x, y; upk(acc2[i][jp], x, y);
            a[i][2 * jp]     = x + bb;
            a[i][2 * jp + 1] = y + bb;
        }
    }

    float2* red2 = reinterpret_cast<float2*>(sWred);
    float fx[4], fy[4];

    #pragma unroll
    for (int jp = 0; jp < 4; jp++) {
        float mx = a[0][2 * jp], my = a[0][2 * jp + 1];
        #pragma unroll
        for (int i = 1; i < 8; i++) {
            mx = fmaxf(mx, a[i][2 * jp]);
            my = fmaxf(my, a[i][2 * jp + 1]);
        }
        red2[w * 128 + jp * 32 + lane] = make_float2(mx, my);
    }
    __syncthreads();
    #pragma unroll
    for (int jp = 0; jp < 4; jp++) {
        float2 m = red2[jp * 32 + lane];
        #pragma unroll
        for (int ww = 1; ww < 8; ww++) {
            float2 o = red2[ww * 128 + jp * 32 + lane];
            m.x = fmaxf(m.x, o.x); m.y = fmaxf(m.y, o.y);
        }
        fx[jp] = m.x; fy[jp] = m.y;
    }
    __syncthreads();

    #pragma unroll
    for (int jp = 0; jp < 4; jp++) {
        float sx = 0.f, sy = 0.f;
        #pragma unroll
        for (int i = 0; i < 8; i++) {
            float ex = __expf(a[i][2 * jp]     - fx[jp]);
            float ey = __expf(a[i][2 * jp + 1] - fy[jp]);
            a[i][2 * jp] = ex; a[i][2 * jp + 1] = ey;
            sx += ex; sy += ey;
        }
        red2[w * 128 + jp * 32 + lane] = make_float2(sx, sy);
    }
    __syncthreads();
    #pragma unroll
    for (int jp = 0; jp < 4; jp++) {
        float2 s = red2[jp * 32 + lane];
        #pragma unroll
        for (int ww = 1; ww < 8; ww++) {
            float2 o = red2[ww * 128 + jp * 32 + lane];
            s.x += o.x; s.y += o.y;
        }
        fx[jp] = 1.f / s.x; fy[jp] = 1.f / s.y;
    }

    __nv_bfloat16* Sb = g_Sbf + (size_t)b * K_ * N_;
    #pragma unroll
    for (int i = 0; i < 8; i++) {
        float srow = 0.f;
        __nv_bfloat16* row = Sb + (size_t)(w * 8 + i) * N_ + n0;
        #pragma unroll
        for (int jp = 0; jp < 4; jp++) {
            float px = a[i][2 * jp] * fx[jp];
            float py = a[i][2 * jp + 1] * fy[jp];
            srow += px + py;
            __nv_bfloat162 bp = __floats2bfloat162_rn(px, py);
            *reinterpret_cast<unsigned*>(row + jp * 64 + lane * 2) =
                *reinterpret_cast<unsigned*>(&bp);
        }
        #pragma unroll
        for (int o = 16; o > 0; o >>= 1)
            srow += __shfl_xor_sync(0xffffffffu, srow, o);
        if (lane == 0) atomicAdd(&g_ssum[b * K_ + w * 8 + i], srow);
    }
}

// ---------------- k2: agg GEMM via mma.sync bf16 (fallback HMMA) ------------
// agg[d,k] = sum_n desc[d,n] * S[k,n].  CTA tile: M=128 (d) x N=64 (k clusters),
// reduce over n-range 1024 in 64-chunks. grid (4, NSPLIT=4, 16), 256 threads.
// Warp layout 4(m) x 2(n): warp tile 32d x 32k = 2 m16 x 4 n8 mma tiles.
// smem rows padded to 144B (128B data + 16B) -> conflict-free ldmatrix.
#define SA_STRIDE 144   // bytes per A row (128 d-rows)
#define SB_STRIDE 144   // bytes per B row (64 k-rows)

__global__ __launch_bounds__(256, 2)
void k2_mma(const float* __restrict__ desc)
{
    __shared__ __align__(16) char sA[128 * SA_STRIDE];   // 18432 B, bf16 [d][n64]
    __shared__ __align__(16) char sB[64 * SB_STRIDE];    //  9216 B, bf16 [k][n64]

    const int t     = threadIdx.x;
    const int lane  = t & 31;
    const int w     = t >> 5;
    const int warpM = w >> 1;   // 0..3
    const int warpN = w & 1;    // 0..1
    const int d0    = blockIdx.x * 128;
    const int ns    = blockIdx.y;
    const int b     = blockIdx.z;

    const float* __restrict__ dB = desc + (size_t)b * D_ * N_;
    const __nv_bfloat16* __restrict__ Sb = g_Sbf + (size_t)b * K_ * N_;

    const unsigned sAu = smem_u32(sA);
    const unsigned sBu = smem_u32(sB);

    float acc[2][4][4];
    #pragma unroll
    for (int mt = 0; mt < 2; mt++)
        #pragma unroll
        for (int nt = 0; nt < 4; nt++)
            #pragma unroll
            for (int q = 0; q < 4; q++) acc[mt][nt][q] = 0.f;

    // precomputed ldmatrix lane addressing
    const int aRow  = (lane & 7) + ((lane >> 3) & 1) * 8;      // 0..15
    const int aKoff = ((lane >> 4) & 1) * 16;                  // byte
    const int bRow  = (lane & 7) + ((lane >> 4) & 1) * 8;      // 0..15 (n-dim)
    const int bKoff = ((lane >> 3) & 1) * 16;                  // byte

    #pragma unroll 1
    for (int c = 0; c < 16; c++) {
        const int n0c = ns * 1024 + c * 64;

        // ---- load A: desc[d0..+127][n0c..+63] fp32 -> bf16 smem ----
        #pragma unroll
        for (int r = 0; r < 8; r++) {
            int idx = r * 256 + t;
            int row = idx >> 4, c4 = idx & 15;
            float4 v = *reinterpret_cast<const float4*>(
                dB + (size_t)(d0 + row) * N_ + n0c + c4 * 4);
            __nv_bfloat162 p0 = __floats2bfloat162_rn(v.x, v.y);
            __nv_bfloat162 p1 = __floats2bfloat162_rn(v.z, v.w);
            unsigned u0 = *reinterpret_cast<unsigned*>(&p0);
            unsigned u1 = *reinterpret_cast<unsigned*>(&p1);
            *reinterpret_cast<uint2*>(sA + row * SA_STRIDE + c4 * 8) =
                make_uint2(u0, u1);
        }
        // ---- load B: S[0..63][n0c..+63] bf16 -> smem ----
        #pragma unroll
        for (int r = 0; r < 2; r++) {
            int idx = r * 256 + t;
            int row = idx >> 3, c16 = idx & 7;
            uint4 v = *reinterpret_cast<const uint4*>(
                Sb + (size_t)row * N_ + n0c + c16 * 8);
            *reinterpret_cast<uint4*>(sB + row * SB_STRIDE + c16 * 16) = v;
        }
        __syncthreads();

        // ---- compute: 4 k-steps of 16 ----
        #pragma unroll
        for (int ks = 0; ks < 4; ks++) {
            unsigned af[2][4];
            #pragma unroll
            for (int mt = 0; mt < 2; mt++) {
                unsigned addr = sAu
                    + (warpM * 32 + mt * 16 + aRow) * SA_STRIDE
                    + ks * 32 + aKoff;
                asm volatile(
                    "ldmatrix.sync.aligned.m8n8.x4.shared.b16 {%0,%1,%2,%3}, [%4];"
                    : "=r"(af[mt][0]), "=r"(af[mt][1]), "=r"(af[mt][2]), "=r"(af[mt][3])
                    : "r"(addr));
            }
            unsigned bf[2][4];
            #pragma unroll
            for (int np = 0; np < 2; np++) {
                unsigned addr = sBu
                    + (warpN * 32 + np * 16 + bRow) * SB_STRIDE
                    + ks * 32 + bKoff;
                asm volatile(
                    "ldmatrix.sync.aligned.m8n8.x4.shared.b16 {%0,%1,%2,%3}, [%4];"
                    : "=r"(bf[np][0]), "=r"(bf[np][1]), "=r"(bf[np][2]), "=r"(bf[np][3])
                    : "r"(addr));
            }
            #pragma unroll
            for (int mt = 0; mt < 2; mt++) {
                #pragma unroll
                for (int nt = 0; nt < 4; nt++) {
                    unsigned b0 = bf[nt >> 1][(nt & 1) * 2 + 0];
                    unsigned b1 = bf[nt >> 1][(nt & 1) * 2 + 1];
                    asm volatile(
                        "mma.sync.aligned.m16n8k16.row.col.f32.bf16.bf16.f32 "
                        "{%0,%1,%2,%3}, {%4,%5,%6,%7}, {%8,%9}, {%0,%1,%2,%3};"
                        : "+f"(acc[mt][nt][0]), "+f"(acc[mt][nt][1]),
                          "+f"(acc[mt][nt][2]), "+f"(acc[mt][nt][3])
                        : "r"(af[mt][0]), "r"(af[mt][1]), "r"(af[mt][2]), "r"(af[mt][3]),
                          "r"(b0), "r"(b1));
                }
            }
        }
        __syncthreads();
    }

    // ---- epilogue: write partials [d][k] (float2 per fragment pair) ----
    float* outp = g_part + ((size_t)ns * B_ + b) * (D_ * K_);
    const int dBase = d0 + warpM * 32 + (lane >> 2);
    const int kBase = warpN * 32 + (lane & 3) * 2;
    #pragma unroll
    for (int mt = 0; mt < 2; mt++) {
        #pragma unroll
        for (int nt = 0; nt < 4; nt++) {
            int kc = kBase + nt * 8;
            int dr = dBase + mt * 16;
            *reinterpret_cast<float2*>(outp + (size_t)dr * K_ + kc) =
                make_float2(acc[mt][nt][0], acc[mt][nt][1]);
            *reinterpret_cast<float2*>(outp + (size_t)(dr + 8) * K_ + kc) =
                make_float2(acc[mt][nt][2], acc[mt][nt][3]);
        }
    }
}

// ---------------- k3: combine partials, subtract centers*ssum, intra-norm ---
// grid (B_, 8) = 128 blocks x 256 threads. Block: (b, 8 k-clusters, all 512 d).
__global__ void k3_vlad(const float* __restrict__ centers, float* __restrict__ out)
{
    const int b  = blockIdx.x;
    const int kg = blockIdx.y;
    const int t  = threadIdx.x;
    const int kq = t & 1;
    const int dg = t >> 1;
    const int kbase = kg * 8 + kq * 4;

    float4 ss4 = *reinterpret_cast<const float4*>(&g_ssum[b * K_ + kbase]);

    float4 v[4];
    float4 sq = make_float4(0.f, 0.f, 0.f, 0.f);
    size_t offs[4];
    #pragma unroll
    for (int r = 0; r < 4; r++) {
        int d = dg + r * 128;
        size_t off = (size_t)d * K_ + kbase;
        offs[r] = off;
        float4 s = make_float4(0.f, 0.f, 0.f, 0.f);
        #pragma unroll
        for (int ns = 0; ns < NSPLIT; ns++) {
            float4 p = *reinterpret_cast<const float4*>(
                &g_part[((size_t)ns * B_ + b) * (D_ * K_) + off]);
            s.x += p.x; s.y += p.y; s.z += p.z; s.w += p.w;
        }
        float4 c4 = *reinterpret_cast<const float4*>(&centers[off]);
        v[r].x = s.x - c4.x * ss4.x;
        v[r].y = s.y - c4.y * ss4.y;
        v[r].z = s.z - c4.z * ss4.z;
        v[r].w = s.w - c4.w * ss4.w;
        sq.x += v[r].x * v[r].x;
        sq.y += v[r].y * v[r].y;
        sq.z += v[r].z * v[r].z;
        sq.w += v[r].w * v[r].w;
    }

    __shared__ float4 sred[256];
    __shared__ float4 sinv[2];
    sred[t] = sq;
    __syncthreads();
    #pragma unroll
    for (int s = 128; s >= 2; s >>= 1) {
        if (t < s) {
            float4 o = sred[t + s];
            sred[t].x += o.x; sred[t].y += o.y;
            sred[t].z += o.z; sred[t].w += o.w;
        }
        __syncthreads();
    }
    if (t < 2) {
        float4 tot = sred[t];
        float4 inv;
        inv.x = 1.f / fmaxf(sqrtf(tot.x), 1e-12f);
        inv.y = 1.f / fmaxf(sqrtf(tot.y), 1e-12f);
        inv.z = 1.f / fmaxf(sqrtf(tot.z), 1e-12f);
        inv.w = 1.f / fmaxf(sqrtf(tot.w), 1e-12f);
        sinv[t] = inv;
        float bn = tot.x * inv.x * inv.x + tot.y * inv.y * inv.y
                 + tot.z * inv.z * inv.z + tot.w * inv.w * inv.w;
        atomicAdd(&g_bnorm[b], bn);
    }
    __syncthreads();
    float4 inv = sinv[kq];
    float* ob = out + (size_t)b * (D_ * K_);
    #pragma unroll
    for (int r = 0; r < 4; r++) {
        float4 o;
        o.x = v[r].x * inv.x;
        o.y = v[r].y * inv.y;
        o.z = v[r].z * inv.z;
        o.w = v[r].w * inv.w;
        *reinterpret_cast<float4*>(&ob[offs[r]]) = o;
    }
}

// ---------------- k4: global L2 normalize ----------------------------------
__global__ void k4_gnorm(float* __restrict__ out)
{
    int idx = blockIdx.x * 256 + threadIdx.x;
    float inv = 1.f / fmaxf(sqrtf(g_bnorm[idx >> 15]), 1e-12f);
    out[idx] *= inv;
}

// ---------------- launch -----------------------------------------------------
extern "C" void kernel_launch(void* const* d_in, const int* in_sizes, int n_in,
                              void* d_out, int out_size)
{
    const float* desc    = (const float*)d_in[0];   // [16,512,4096]
    const float* W       = (const float*)d_in[1];   // [64,512]
    const float* bias    = (const float*)d_in[2];   // [64]
    const float* centers = (const float*)d_in[3];   // [512,64]
    float* out = (float*)d_out;                      // [16, 512*64]

    k0_zero<<<4, 256>>>();
    k1_scores<<<dim3(N_ / 256, B_), 256>>>(desc, W, bias);
    k2_mma<<<dim3(D_ / 128, NSPLIT, B_), 256>>>(desc);
    k3_vlad<<<dim3(B_, 8), 256>>>(centers, out);
    k4_gnorm<<<(B_ * D_ * K_) / 256, 256>>>(out);
}

// round 6
// speedup vs baseline: 3.5523x; 2.0612x over previous
#include <cuda_runtime.h>
#include <cuda_bf16.h>
#include <math.h>
#include <stdint.h>

typedef unsigned long long ull;

#define B_ 16
#define D_ 512
#define K_ 64
#define N_ 4096
#define NSPLIT 4

// ---------------- scratch (device globals: no runtime allocation) ----------
__device__ __nv_bfloat16 g_Sbf[(size_t)B_ * K_ * N_];       // softmax scores bf16 [b][k][n]
__device__ float g_ssum[B_ * K_];                           // sum_n S (fp32)
__device__ float g_part[(size_t)NSPLIT * B_ * D_ * K_];     // agg partials [ns][b][d][k]
__device__ float g_bnorm[B_];                               // per-b global sum-of-squares

__device__ __forceinline__ unsigned smem_u32(const void* p) {
    unsigned a;
    asm("{ .reg .u64 t; cvta.to.shared.u64 t, %1; cvt.u32.u64 %0, t; }" : "=r"(a) : "l"(p));
    return a;
}

// ---------------- k0: zero accumulators ------------------------------------
__global__ void k0_zero() {
    int t = blockIdx.x * 256 + threadIdx.x;
    if (t < B_ * K_) g_ssum[t] = 0.f;
    if (t < B_)      g_bnorm[t] = 0.f;
}

// ---------------- k1: logits via mma.sync bf16 + softmax + ssum -------------
// logits[k,n] = sum_d W[k,d] * desc[d,n].  CTA: 64 k x 256 n, reduce D in 64s.
// grid (N_/256=16, B_), 256 threads (8 warps). Warp w owns n-slice [w*32, w*32+32),
// ALL 64 k -> softmax fully warp-local. A = W (normal ldmatrix), B = desc [d][n]
// via ldmatrix.x4.trans.
#define XSTRIDE 528   // 256 bf16 cols * 2 + 16 pad
#define WSTRIDE 144   // 64 bf16 cols * 2 + 16 pad

__global__ __launch_bounds__(256, 2)
void k1_mma(const float* __restrict__ desc, const float* __restrict__ W,
            const float* __restrict__ bias)
{
    __shared__ __align__(16) char sX[64 * XSTRIDE];   // desc chunk [d64][n256] bf16; reused for S
    __shared__ __align__(16) char sW[64 * WSTRIDE];   // W chunk [k64][d64] bf16
    __shared__ float sBias[64];
    __shared__ float sSum[64];

    const int b    = blockIdx.y;
    const int n0   = blockIdx.x * 256;
    const int t    = threadIdx.x;
    const int lane = t & 31;
    const int w    = t >> 5;

    const float* __restrict__ dB = desc + (size_t)b * D_ * N_;

    if (t < 64) { sBias[t] = bias[t]; sSum[t] = 0.f; }

    const unsigned sXu = smem_u32(sX);
    const unsigned sWu = smem_u32(sW);

    float acc[4][4][4];   // [mt(k16)][nt(n8)][frag]
    #pragma unroll
    for (int mt = 0; mt < 4; mt++)
        #pragma unroll
        for (int nt = 0; nt < 4; nt++)
            #pragma unroll
            for (int q = 0; q < 4; q++) acc[mt][nt][q] = 0.f;

    // ldmatrix lane addressing
    const int aRow  = (lane & 7) + ((lane >> 3) & 1) * 8;   // A (normal)
    const int aKoff = ((lane >> 4) & 1) * 16;
    const int bDrow = ((lane >> 3) & 1) * 8 + (lane & 7);   // B (trans): d-row within k16
    const int bNoff = ((lane >> 4) & 1) * 8;                // n offset (elements)

    #pragma unroll 1
    for (int c = 0; c < 8; c++) {
        const int d0c = c * 64;
        // ---- load W chunk: W[0..63][d0c..+63] fp32 -> bf16 smem ----
        #pragma unroll
        for (int r = 0; r < 4; r++) {
            int idx = r * 256 + t;
            int row = idx >> 4, c4 = idx & 15;
            float4 v = *reinterpret_cast<const float4*>(W + (size_t)row * D_ + d0c + c4 * 4);
            __nv_bfloat162 p0 = __floats2bfloat162_rn(v.x, v.y);
            __nv_bfloat162 p1 = __floats2bfloat162_rn(v.z, v.w);
            *reinterpret_cast<uint2*>(sW + row * WSTRIDE + c4 * 8) =
                make_uint2(*reinterpret_cast<unsigned*>(&p0), *reinterpret_cast<unsigned*>(&p1));
        }
        // ---- load desc chunk: desc[d0c..+63][n0..+255] fp32 -> bf16 smem ----
        #pragma unroll
        for (int r = 0; r < 16; r++) {
            int idx = r * 256 + t;
            int row = idx >> 6, c4 = idx & 63;
            float4 v = *reinterpret_cast<const float4*>(
                dB + (size_t)(d0c + row) * N_ + n0 + c4 * 4);
            __nv_bfloat162 p0 = __floats2bfloat162_rn(v.x, v.y);
            __nv_bfloat162 p1 = __floats2bfloat162_rn(v.z, v.w);
            *reinterpret_cast<uint2*>(sX + row * XSTRIDE + c4 * 8) =
                make_uint2(*reinterpret_cast<unsigned*>(&p0), *reinterpret_cast<unsigned*>(&p1));
        }
        __syncthreads();

        // ---- compute: 4 k-steps of 16 over d ----
        #pragma unroll
        for (int ks = 0; ks < 4; ks++) {
            unsigned af[4][4];
            #pragma unroll
            for (int mt = 0; mt < 4; mt++) {
                unsigned addr = sWu + (mt * 16 + aRow) * WSTRIDE + ks * 32 + aKoff;
                asm volatile(
                    "ldmatrix.sync.aligned.m8n8.x4.shared.b16 {%0,%1,%2,%3}, [%4];"
                    : "=r"(af[mt][0]), "=r"(af[mt][1]), "=r"(af[mt][2]), "=r"(af[mt][3])
                    : "r"(addr));
            }
            unsigned bf[2][4];
            #pragma unroll
            for (int np = 0; np < 2; np++) {
                unsigned addr = sXu + (ks * 16 + bDrow) * XSTRIDE
                              + (w * 32 + np * 16 + bNoff) * 2;
                asm volatile(
                    "ldmatrix.sync.aligned.m8n8.x4.trans.shared.b16 {%0,%1,%2,%3}, [%4];"
                    : "=r"(bf[np][0]), "=r"(bf[np][1]), "=r"(bf[np][2]), "=r"(bf[np][3])
                    : "r"(addr));
            }
            #pragma unroll
            for (int mt = 0; mt < 4; mt++) {
                #pragma unroll
                for (int nt = 0; nt < 4; nt++) {
                    unsigned b0 = bf[nt >> 1][(nt & 1) * 2 + 0];
                    unsigned b1 = bf[nt >> 1][(nt & 1) * 2 + 1];
                    asm volatile(
                        "mma.sync.aligned.m16n8k16.row.col.f32.bf16.bf16.f32 "
                        "{%0,%1,%2,%3}, {%4,%5,%6,%7}, {%8,%9}, {%0,%1,%2,%3};"
                        : "+f"(acc[mt][nt][0]), "+f"(acc[mt][nt][1]),
                          "+f"(acc[mt][nt][2]), "+f"(acc[mt][nt][3])
                        : "r"(af[mt][0]), "r"(af[mt][1]), "r"(af[mt][2]), "r"(af[mt][3]),
                          "r"(b0), "r"(b1));
                }
            }
        }
        __syncthreads();
    }

    // ---- softmax over k (warp-local) ----
    // frag: q0:(g, col) q1:(g, col+1) q2:(g+8, col) q3:(g+8, col+1)
    // k = mt*16 + g (+8 for q>=2), col = nt*8 + (lane&3)*2 within warp n-slice
    const int g = lane >> 2;

    // bias
    #pragma unroll
    for (int mt = 0; mt < 4; mt++) {
        float b0v = sBias[mt * 16 + g];
        float b1v = sBias[mt * 16 + g + 8];
        #pragma unroll
        for (int nt = 0; nt < 4; nt++) {
            acc[mt][nt][0] += b0v; acc[mt][nt][1] += b0v;
            acc[mt][nt][2] += b1v; acc[mt][nt][3] += b1v;
        }
    }

    // per-column max over 64 k
    float cmax[4][2];
    #pragma unroll
    for (int nt = 0; nt < 4; nt++) {
        #pragma unroll
        for (int par = 0; par < 2; par++) {
            float m = fmaxf(acc[0][nt][par], acc[0][nt][2 + par]);
            #pragma unroll
            for (int mt = 1; mt < 4; mt++)
                m = fmaxf(m, fmaxf(acc[mt][nt][par], acc[mt][nt][2 + par]));
            #pragma unroll
            for (int o = 4; o <= 16; o <<= 1)
                m = fmaxf(m, __shfl_xor_sync(0xffffffffu, m, o));
            cmax[nt][par] = m;
        }
    }
    // exp + per-column sum
    float cinv[4][2];
    #pragma unroll
    for (int nt = 0; nt < 4; nt++) {
        #pragma unroll
        for (int par = 0; par < 2; par++) {
            float s = 0.f;
            #pragma unroll
            for (int mt = 0; mt < 4; mt++) {
                float e0 = __expf(acc[mt][nt][par]     - cmax[nt][par]);
                float e1 = __expf(acc[mt][nt][2 + par] - cmax[nt][par]);
                acc[mt][nt][par] = e0; acc[mt][nt][2 + par] = e1;
                s += e0 + e1;
            }
            #pragma unroll
            for (int o = 4; o <= 16; o <<= 1)
                s += __shfl_xor_sync(0xffffffffu, s, o);
            cinv[nt][par] = 1.f / s;
        }
    }
    // normalize in regs
    #pragma unroll
    for (int nt = 0; nt < 4; nt++)
        #pragma unroll
        for (int par = 0; par < 2; par++) {
            float inv = cinv[nt][par];
            #pragma unroll
            for (int mt = 0; mt < 4; mt++) {
                acc[mt][nt][par]     *= inv;
                acc[mt][nt][2 + par] *= inv;
            }
        }

    // ssum per k: sum over this thread's 8 columns, reduce over lane&3
    #pragma unroll
    for (int mt = 0; mt < 4; mt++) {
        #pragma unroll
        for (int h = 0; h < 2; h++) {
            float s = 0.f;
            #pragma unroll
            for (int nt = 0; nt < 4; nt++)
                s += acc[mt][nt][h * 2] + acc[mt][nt][h * 2 + 1];
            s += __shfl_xor_sync(0xffffffffu, s, 1);
            s += __shfl_xor_sync(0xffffffffu, s, 2);
            if ((lane & 3) == 0)
                atomicAdd(&sSum[mt * 16 + g + h * 8], s);
        }
    }

    // store S to smem (reuse sX region), bf16x2 per store
    #pragma unroll
    for (int mt = 0; mt < 4; mt++) {
        #pragma unroll
        for (int h = 0; h < 2; h++) {
            int k = mt * 16 + g + h * 8;
            #pragma unroll
            for (int nt = 0; nt < 4; nt++) {
                __nv_bfloat162 p = __floats2bfloat162_rn(acc[mt][nt][h * 2],
                                                         acc[mt][nt][h * 2 + 1]);
                *reinterpret_cast<unsigned*>(
                    sX + k * XSTRIDE + (w * 32 + nt * 8 + (lane & 3) * 2) * 2) =
                    *reinterpret_cast<unsigned*>(&p);
            }
        }
    }
    __syncthreads();

    // coalesced copy S -> global, ssum -> global
    __nv_bfloat16* Sb = g_Sbf + (size_t)b * K_ * N_ + n0;
    #pragma unroll
    for (int r = 0; r < 8; r++) {
        int idx = r * 256 + t;
        int k = idx >> 5, c16 = idx & 31;
        uint4 v = *reinterpret_cast<const uint4*>(sX + k * XSTRIDE + c16 * 16);
        *reinterpret_cast<uint4*>(Sb + (size_t)k * N_ + c16 * 8) = v;
    }
    if (t < 64) atomicAdd(&g_ssum[b * K_ + t], sSum[t]);
}

// ---------------- k2: agg GEMM via mma.sync bf16 (unchanged from R5) --------
#define SA_STRIDE 144
#define SB_STRIDE 144

__global__ __launch_bounds__(256, 2)
void k2_mma(const float* __restrict__ desc)
{
    __shared__ __align__(16) char sA[128 * SA_STRIDE];
    __shared__ __align__(16) char sB[64 * SB_STRIDE];

    const int t     = threadIdx.x;
    const int lane  = t & 31;
    const int w     = t >> 5;
    const int warpM = w >> 1;
    const int warpN = w & 1;
    const int d0    = blockIdx.x * 128;
    const int ns    = blockIdx.y;
    const int b     = blockIdx.z;

    const float* __restrict__ dB = desc + (size_t)b * D_ * N_;
    const __nv_bfloat16* __restrict__ Sb = g_Sbf + (size_t)b * K_ * N_;

    const unsigned sAu = smem_u32(sA);
    const unsigned sBu = smem_u32(sB);

    float acc[2][4][4];
    #pragma unroll
    for (int mt = 0; mt < 2; mt++)
        #pragma unroll
        for (int nt = 0; nt < 4; nt++)
            #pragma unroll
            for (int q = 0; q < 4; q++) acc[mt][nt][q] = 0.f;

    const int aRow  = (lane & 7) + ((lane >> 3) & 1) * 8;
    const int aKoff = ((lane >> 4) & 1) * 16;
    const int bRow  = (lane & 7) + ((lane >> 4) & 1) * 8;
    const int bKoff = ((lane >> 3) & 1) * 16;

    #pragma unroll 1
    for (int c = 0; c < 16; c++) {
        const int n0c = ns * 1024 + c * 64;

        #pragma unroll
        for (int r = 0; r < 8; r++) {
            int idx = r * 256 + t;
            int row = idx >> 4, c4 = idx & 15;
            float4 v = *reinterpret_cast<const float4*>(
                dB + (size_t)(d0 + row) * N_ + n0c + c4 * 4);
            __nv_bfloat162 p0 = __floats2bfloat162_rn(v.x, v.y);
            __nv_bfloat162 p1 = __floats2bfloat162_rn(v.z, v.w);
            *reinterpret_cast<uint2*>(sA + row * SA_STRIDE + c4 * 8) =
                make_uint2(*reinterpret_cast<unsigned*>(&p0), *reinterpret_cast<unsigned*>(&p1));
        }
        #pragma unroll
        for (int r = 0; r < 2; r++) {
            int idx = r * 256 + t;
            int row = idx >> 3, c16 = idx & 7;
            uint4 v = *reinterpret_cast<const uint4*>(
                Sb + (size_t)row * N_ + n0c + c16 * 8);
            *reinterpret_cast<uint4*>(sB + row * SB_STRIDE + c16 * 16) = v;
        }
        __syncthreads();

        #pragma unroll
        for (int ks = 0; ks < 4; ks++) {
            unsigned af[2][4];
            #pragma unroll
            for (int mt = 0; mt < 2; mt++) {
                unsigned addr = sAu + (warpM * 32 + mt * 16 + aRow) * SA_STRIDE
                              + ks * 32 + aKoff;
                asm volatile(
                    "ldmatrix.sync.aligned.m8n8.x4.shared.b16 {%0,%1,%2,%3}, [%4];"
                    : "=r"(af[mt][0]), "=r"(af[mt][1]), "=r"(af[mt][2]), "=r"(af[mt][3])
                    : "r"(addr));
            }
            unsigned bf[2][4];
            #pragma unroll
            for (int np = 0; np < 2; np++) {
                unsigned addr = sBu + (warpN * 32 + np * 16 + bRow) * SB_STRIDE
                              + ks * 32 + bKoff;
                asm volatile(
                    "ldmatrix.sync.aligned.m8n8.x4.shared.b16 {%0,%1,%2,%3}, [%4];"
                    : "=r"(bf[np][0]), "=r"(bf[np][1]), "=r"(bf[np][2]), "=r"(bf[np][3])
                    : "r"(addr));
            }
            #pragma unroll
            for (int mt = 0; mt < 2; mt++) {
                #pragma unroll
                for (int nt = 0; nt < 4; nt++) {
                    unsigned b0 = bf[nt >> 1][(nt & 1) * 2 + 0];
                    unsigned b1 = bf[nt >> 1][(nt & 1) * 2 + 1];
                    asm volatile(
                        "mma.sync.aligned.m16n8k16.row.col.f32.bf16.bf16.f32 "
                        "{%0,%1,%2,%3}, {%4,%5,%6,%7}, {%8,%9}, {%0,%1,%2,%3};"
                        : "+f"(acc[mt][nt][0]), "+f"(acc[mt][nt][1]),
                          "+f"(acc[mt][nt][2]), "+f"(acc[mt][nt][3])
                        : "r"(af[mt][0]), "r"(af[mt][1]), "r"(af[mt][2]), "r"(af[mt][3]),
                          "r"(b0), "r"(b1));
                }
            }
        }
        __syncthreads();
    }

    float* outp = g_part + ((size_t)ns * B_ + b) * (D_ * K_);
    const int dBase = d0 + warpM * 32 + (lane >> 2);
    const int kBase = warpN * 32 + (lane & 3) * 2;
    #pragma unroll
    for (int mt = 0; mt < 2; mt++) {
        #pragma unroll
        for (int nt = 0; nt < 4; nt++) {
            int kc = kBase + nt * 8;
            int dr = dBase + mt * 16;
            *reinterpret_cast<float2*>(outp + (size_t)dr * K_ + kc) =
                make_float2(acc[mt][nt][0], acc[mt][nt][1]);
            *reinterpret_cast<float2*>(outp + (size_t)(dr + 8) * K_ + kc) =
                make_float2(acc[mt][nt][2], acc[mt][nt][3]);
        }
    }
}

// ---------------- k3: combine partials, subtract centers*ssum, intra-norm ---
__global__ void k3_vlad(const float* __restrict__ centers, float* __restrict__ out)
{
    const int b  = blockIdx.x;
    const int kg = blockIdx.y;
    const int t  = threadIdx.x;
    const int kq = t & 1;
    const int dg = t >> 1;
    const int kbase = kg * 8 + kq * 4;

    float4 ss4 = *reinterpret_cast<const float4*>(&g_ssum[b * K_ + kbase]);

    float4 v[4];
    float4 sq = make_float4(0.f, 0.f, 0.f, 0.f);
    size_t offs[4];
    #pragma unroll
    for (int r = 0; r < 4; r++) {
        int d = dg + r * 128;
        size_t off = (size_t)d * K_ + kbase;
        offs[r] = off;
        float4 s = make_float4(0.f, 0.f, 0.f, 0.f);
        #pragma unroll
        for (int ns = 0; ns < NSPLIT; ns++) {
            float4 p = *reinterpret_cast<const float4*>(
                &g_part[((size_t)ns * B_ + b) * (D_ * K_) + off]);
            s.x += p.x; s.y += p.y; s.z += p.z; s.w += p.w;
        }
        float4 c4 = *reinterpret_cast<const float4*>(&centers[off]);
        v[r].x = s.x - c4.x * ss4.x;
        v[r].y = s.y - c4.y * ss4.y;
        v[r].z = s.z - c4.z * ss4.z;
        v[r].w = s.w - c4.w * ss4.w;
        sq.x += v[r].x * v[r].x;
        sq.y += v[r].y * v[r].y;
        sq.z += v[r].z * v[r].z;
        sq.w += v[r].w * v[r].w;
    }

    __shared__ float4 sred[256];
    __shared__ float4 sinv[2];
    sred[t] = sq;
    __syncthreads();
    #pragma unroll
    for (int s = 128; s >= 2; s >>= 1) {
        if (t < s) {
            float4 o = sred[t + s];
            sred[t].x += o.x; sred[t].y += o.y;
            sred[t].z += o.z; sred[t].w += o.w;
        }
        __syncthreads();
    }
    if (t < 2) {
        float4 tot = sred[t];
        float4 inv;
        inv.x = 1.f / fmaxf(sqrtf(tot.x), 1e-12f);
        inv.y = 1.f / fmaxf(sqrtf(tot.y), 1e-12f);
        inv.z = 1.f / fmaxf(sqrtf(tot.z), 1e-12f);
        inv.w = 1.f / fmaxf(sqrtf(tot.w), 1e-12f);
        sinv[t] = inv;
        float bn = tot.x * inv.x * inv.x + tot.y * inv.y * inv.y
                 + tot.z * inv.z * inv.z + tot.w * inv.w * inv.w;
        atomicAdd(&g_bnorm[b], bn);
    }
    __syncthreads();
    float4 inv = sinv[kq];
    float* ob = out + (size_t)b * (D_ * K_);
    #pragma unroll
    for (int r = 0; r < 4; r++) {
        float4 o;
        o.x = v[r].x * inv.x;
        o.y = v[r].y * inv.y;
        o.z = v[r].z * inv.z;
        o.w = v[r].w * inv.w;
        *reinterpret_cast<float4*>(&ob[offs[r]]) = o;
    }
}

// ---------------- k4: global L2 normalize ----------------------------------
__global__ void k4_gnorm(float* __restrict__ out)
{
    int idx = blockIdx.x * 256 + threadIdx.x;
    float inv = 1.f / fmaxf(sqrtf(g_bnorm[idx >> 15]), 1e-12f);
    out[idx] *= inv;
}

// ---------------- launch -----------------------------------------------------
extern "C" void kernel_launch(void* const* d_in, const int* in_sizes, int n_in,
                              void* d_out, int out_size)
{
    const float* desc    = (const float*)d_in[0];   // [16,512,4096]
    const float* W       = (const float*)d_in[1];   // [64,512]
    const float* bias    = (const float*)d_in[2];   // [64]
    const float* centers = (const float*)d_in[3];   // [512,64]
    float* out = (float*)d_out;                      // [16, 512*64]

    k0_zero<<<4, 256>>>();
    k1_mma<<<dim3(N_ / 256, B_), 256>>>(desc, W, bias);
    k2_mma<<<dim3(D_ / 128, NSPLIT, B_), 256>>>(desc);
    k3_vlad<<<dim3(B_, 8), 256>>>(centers, out);
    k4_gnorm<<<(B_ * D_ * K_) / 256, 256>>>(out);
}